// round 11
// baseline (speedup 1.0000x reference)
#include <cuda_runtime.h>
#include <cstdint>

// Problem constants
#define NM 100000
#define NT 100000
#define NE 400000
#define DD 128
#define K2 256
#define NMAX 100000

#define CDIV(a,b) (((a)+(b)-1)/(b))

// ---------------- scratch ----------------
__device__ float4 g_agg_t[(size_t)NT * DD / 4];
__device__ float4 g_agg_m[(size_t)NM * DD / 4];
__device__ float4 g_bm0[(size_t)NM * DD / 4];
__device__ float4 g_bm1[(size_t)NM * DD / 4];
__device__ float4 g_bt0[(size_t)NT * DD / 4];
__device__ float4 g_bt1[(size_t)NT * DD / 4];
__device__ float4 g_inv_t[NT / 4];
__device__ float4 g_inv_m[NM / 4];
__device__ float4 g_Bext[3 * 2 * K2 * DD / 4];   // [layer][type][k][j] tf32 bits
__device__ int    g_e32_mt[2 * NE];
__device__ int    g_e32_tm[2 * NE];
__device__ int    g_is32;

__device__ __forceinline__ uint32_t f2tf32(float f) {
    uint32_t r;
    asm("cvt.rna.tf32.f32 %0, %1;" : "=r"(r) : "f"(f));
    return r;
}
__device__ __forceinline__ uint32_t smem_u32(const void* p) {
    uint32_t a;
    asm("{ .reg .u64 t; cvta.to.shared.u64 t, %1; cvt.u32.u64 %0, t; }" : "=r"(a) : "l"(p));
    return a;
}

// ---------------- edge dtype detect + convert ----------------
__global__ void detect_reset() { g_is32 = 0; }
__global__ void detect_kernel(const unsigned* __restrict__ p) {
    int i = blockIdx.x * blockDim.x + threadIdx.x;
    unsigned v = 0;
    for (int w = i * 2 + 1; w < 2 * NE; w += gridDim.x * blockDim.x * 2) v |= p[w];
    if (__syncthreads_or(v != 0) && threadIdx.x == 0) atomicExch(&g_is32, 1);
}
__global__ void convert_kernel(const void* __restrict__ e, int* __restrict__ out) {
    int i = blockIdx.x * blockDim.x + threadIdx.x;
    if (i >= 2 * NE) return;
    int v;
    if (g_is32) v = ((const int*)e)[i];
    else        v = (int)((const long long*)e)[i];
    out[i] = min(max(v, 0), NMAX - 1);
}

// ---------------- utilities ----------------
__global__ void zero_two(float4* p0, int n0, float4* p1, int n1) {
    int i = blockIdx.x * blockDim.x + threadIdx.x;
    int stride = gridDim.x * blockDim.x;
    float4 z = make_float4(0.f, 0.f, 0.f, 0.f);
    for (int k = i; k < n0; k += stride) p0[k] = z;
    for (int k = i; k < n1; k += stride) p1[k] = z;
}
__global__ void zero_kernel(float4* p, int n4) {
    int i = blockIdx.x * blockDim.x + threadIdx.x;
    int stride = gridDim.x * blockDim.x;
    float4 z = make_float4(0.f, 0.f, 0.f, 0.f);
    for (; i < n4; i += stride) p[i] = z;
}
// Bext[lt][k][j] = tf32bits( k<128 ? Wl[lt][j][k] : Wr[lt][j][k-128] )
__global__ void prep_weights(const float* __restrict__ Wl,
                             const float* __restrict__ Wr,
                             uint32_t* __restrict__ Bext) {
    int i = blockIdx.x * blockDim.x + threadIdx.x;
    if (i >= 3 * 2 * K2 * DD) return;
    int j  = i % DD;
    int k  = (i / DD) % K2;
    int lt = i / (DD * K2);
    float v = (k < DD) ? Wl[((size_t)lt * DD + j) * DD + k]
                       : Wr[((size_t)lt * DD + j) * DD + (k - DD)];
    Bext[i] = f2tf32(v);
}
__global__ void count_kernel(const int* __restrict__ edge, float* __restrict__ cnt) {
    int i = blockIdx.x * blockDim.x + threadIdx.x;
    if (i < NE) atomicAdd(&cnt[edge[NE + i]], 1.0f);
}
__global__ void invert_kernel(float* __restrict__ c, int n) {
    int i = blockIdx.x * blockDim.x + threadIdx.x;
    if (i < n) c[i] = 1.0f / fmaxf(c[i], 1.0f);
}

// ---------------- scatter via TMA bulk-reduce, inv pre-scaled ----------------
#define EPW 4
__global__ void __launch_bounds__(256)
scatter_bulk(const float* __restrict__ xsrc, const int* __restrict__ edge,
             const float* __restrict__ inv, float* __restrict__ agg) {
    __shared__ __align__(16) float smem[8][EPW][DD];
    const int wInB = threadIdx.x >> 5;
    const int lane = threadIdx.x & 31;
    const int gw = (blockIdx.x * blockDim.x + threadIdx.x) >> 5;
    const int base = gw * EPW;
    if (base >= NE) return;
    const int nE = min(EPW, NE - base);
    const float4* X = (const float4*)xsrc;

#pragma unroll
    for (int j = 0; j < EPW; j++) {
        if (j < nE) {
            int src = edge[base + j];
            float s = inv[edge[NE + base + j]];
            float4 v = X[(size_t)src * (DD / 4) + lane];
            ((float4*)smem[wInB][j])[lane] =
                make_float4(v.x * s, v.y * s, v.z * s, v.w * s);
        }
    }
    __syncwarp();
    if (lane == 0) {
        asm volatile("fence.proxy.async.shared::cta;" ::: "memory");
#pragma unroll
        for (int j = 0; j < EPW; j++) {
            if (j < nE) {
                int dst = edge[NE + base + j];
                float* gp = agg + (size_t)dst * DD;
                uint32_t sa = smem_u32(&smem[wInB][j][0]);
                asm volatile(
                    "cp.reduce.async.bulk.global.shared::cta.bulk_group.add.f32 "
                    "[%0], [%1], %2;" :: "l"(gp), "r"(sa), "r"(DD * 4) : "memory");
            }
        }
        asm volatile("cp.async.bulk.commit_group;" ::: "memory");
        asm volatile("cp.async.bulk.wait_group 0;" ::: "memory");
    }
}

// ---------------- tf32 mma.sync GEMM, register double-buffered ------------
// C[i,j] = sum_{k<256} Aext[i,k]*B[k,j] + bias[j]; Aext = [agg(prescaled) | x]
__global__ void __launch_bounds__(256)
gemm_sage_tc(const float* __restrict__ Aagg,
             const float* __restrict__ Xdst, const uint32_t* __restrict__ B,
             const float* __restrict__ bias, float* __restrict__ Cout,
             int nRows, int relu) {
    __shared__ uint32_t As[128][36];
    __shared__ uint32_t Bs[32][136];

    const int tid  = threadIdx.x;
    const int wid  = tid >> 5;
    const int lane = tid & 31;
    const int g    = lane >> 2;
    const int t    = lane & 3;
    const int m0   = (wid & 1) * 64;
    const int n0   = (wid >> 1) * 32;
    const int rowBase = blockIdx.x * 128;

    float acc[4][4][4];
#pragma unroll
    for (int im = 0; im < 4; im++)
#pragma unroll
        for (int in = 0; in < 4; in++)
#pragma unroll
            for (int q = 0; q < 4; q++) acc[im][in][q] = 0.f;

    float4 ra[4];
    uint4  rb[4];

    // ---- tile fetch into registers (independent LDGs, MLP=8) ----
    auto loadTile = [&](int kt) {
#pragma unroll
        for (int p = 0; p < 4; p++) {
            int f = tid + p * 256;
            int r = f >> 3;
            int q = f & 7;
            int gr = rowBase + r;
            if (gr >= nRows) gr = nRows - 1;
            int kg = kt + q * 4;
            const float* src = (kg < DD) ? (Aagg + (size_t)gr * DD + kg)
                                         : (Xdst + (size_t)gr * DD + (kg - DD));
            ra[p] = *(const float4*)src;
        }
#pragma unroll
        for (int p = 0; p < 4; p++) {
            int f = tid + p * 256;
            int kr = f >> 5;
            int c  = f & 31;
            rb[p] = *(const uint4*)(B + (size_t)(kt + kr) * DD + c * 4);
        }
    };
    // ---- registers -> smem (with A cvt to tf32) ----
    auto storeTile = [&]() {
#pragma unroll
        for (int p = 0; p < 4; p++) {
            int f = tid + p * 256;
            int r = f >> 3;
            int q = f & 7;
            As[r][q * 4 + 0] = f2tf32(ra[p].x);
            As[r][q * 4 + 1] = f2tf32(ra[p].y);
            As[r][q * 4 + 2] = f2tf32(ra[p].z);
            As[r][q * 4 + 3] = f2tf32(ra[p].w);
        }
#pragma unroll
        for (int p = 0; p < 4; p++) {
            int f = tid + p * 256;
            int kr = f >> 5;
            int c  = f & 31;
            *(uint4*)&Bs[kr][c * 4] = rb[p];
        }
    };

    loadTile(0);
    storeTile();
    __syncthreads();

#pragma unroll
    for (int kt = 0; kt < K2; kt += 32) {
        if (kt + 32 < K2) loadTile(kt + 32);   // prefetch overlaps the MMAs below

#pragma unroll
        for (int kk = 0; kk < 32; kk += 8) {
            uint32_t a[4][4], b[4][2];
#pragma unroll
            for (int im = 0; im < 4; im++) {
                int rm = m0 + im * 16 + g;
                a[im][0] = As[rm][kk + t];
                a[im][1] = As[rm + 8][kk + t];
                a[im][2] = As[rm][kk + t + 4];
                a[im][3] = As[rm + 8][kk + t + 4];
            }
#pragma unroll
            for (int in = 0; in < 4; in++) {
                int cn = n0 + in * 8 + g;
                b[in][0] = Bs[kk + t][cn];
                b[in][1] = Bs[kk + t + 4][cn];
            }
#pragma unroll
            for (int im = 0; im < 4; im++)
#pragma unroll
                for (int in = 0; in < 4; in++) {
                    asm volatile(
                        "mma.sync.aligned.m16n8k8.row.col.f32.tf32.tf32.f32 "
                        "{%0,%1,%2,%3}, {%4,%5,%6,%7}, {%8,%9}, {%0,%1,%2,%3};"
                        : "+f"(acc[im][in][0]), "+f"(acc[im][in][1]),
                          "+f"(acc[im][in][2]), "+f"(acc[im][in][3])
                        : "r"(a[im][0]), "r"(a[im][1]), "r"(a[im][2]), "r"(a[im][3]),
                          "r"(b[in][0]), "r"(b[in][1]));
                }
        }
        __syncthreads();
        if (kt + 32 < K2) {
            storeTile();
            __syncthreads();
        }
    }

#pragma unroll
    for (int in = 0; in < 4; in++) {
        int col = n0 + in * 8 + 2 * t;
        float b0 = bias[col], b1 = bias[col + 1];
#pragma unroll
        for (int im = 0; im < 4; im++) {
            int r0 = rowBase + m0 + im * 16 + g;
            float v0 = acc[im][in][0] + b0;
            float v1 = acc[im][in][1] + b1;
            float v2 = acc[im][in][2] + b0;
            float v3 = acc[im][in][3] + b1;
            if (relu) {
                v0 = fmaxf(v0, 0.f); v1 = fmaxf(v1, 0.f);
                v2 = fmaxf(v2, 0.f); v3 = fmaxf(v3, 0.f);
            }
            if (r0 < nRows)
                *(float2*)(Cout + (size_t)r0 * DD + col) = make_float2(v0, v1);
            if (r0 + 8 < nRows)
                *(float2*)(Cout + (size_t)(r0 + 8) * DD + col) = make_float2(v2, v3);
        }
    }
}

// ---------------- launch: two-stream fork/join ----------------
extern "C" void kernel_launch(void* const* d_in, const int* in_sizes, int n_in,
                              void* d_out, int out_size) {
    static bool s_init = false;
    static cudaStream_t sT, sM;
    static cudaEvent_t evFork, evGT[3], evGM[3];
    if (!s_init) {
        cudaStreamCreateWithFlags(&sT, cudaStreamNonBlocking);
        cudaStreamCreateWithFlags(&sM, cudaStreamNonBlocking);
        cudaEventCreateWithFlags(&evFork, cudaEventDisableTiming);
        for (int i = 0; i < 3; i++) {
            cudaEventCreateWithFlags(&evGT[i], cudaEventDisableTiming);
            cudaEventCreateWithFlags(&evGM[i], cudaEventDisableTiming);
        }
        s_init = true;
    }

    const float* x_m = (const float*)d_in[0];
    const float* x_t = (const float*)d_in[1];
    const float* Wl  = (const float*)d_in[2];
    const float* bl  = (const float*)d_in[3];
    const float* Wr  = (const float*)d_in[4];
    const void*  e_mt = d_in[5];
    const void*  e_tm = d_in[6];
    float* out = (float*)d_out;

    float *agg_t, *agg_m, *bm0, *bm1, *bt0, *bt1, *inv_t, *inv_m;
    uint32_t* Bext;
    int *e32_mt, *e32_tm;
    cudaGetSymbolAddress((void**)&agg_t, g_agg_t);
    cudaGetSymbolAddress((void**)&agg_m, g_agg_m);
    cudaGetSymbolAddress((void**)&bm0, g_bm0);
    cudaGetSymbolAddress((void**)&bm1, g_bm1);
    cudaGetSymbolAddress((void**)&bt0, g_bt0);
    cudaGetSymbolAddress((void**)&bt1, g_bt1);
    cudaGetSymbolAddress((void**)&inv_t, g_inv_t);
    cudaGetSymbolAddress((void**)&inv_m, g_inv_m);
    cudaGetSymbolAddress((void**)&Bext, g_Bext);
    cudaGetSymbolAddress((void**)&e32_mt, g_e32_mt);
    cudaGetSymbolAddress((void**)&e32_tm, g_e32_tm);

    const int scatterBlocks = CDIV(CDIV(NE, EPW) * 32, 256);
    const int aggT4 = NT * DD / 4;
    const int aggM4 = NM * DD / 4;

    // preproc on origin stream
    detect_reset<<<1, 1>>>();
    detect_kernel<<<256, 256>>>((const unsigned*)e_mt);
    convert_kernel<<<CDIV(2 * NE, 256), 256>>>(e_mt, e32_mt);
    convert_kernel<<<CDIV(2 * NE, 256), 256>>>(e_tm, e32_tm);
    prep_weights<<<CDIV(3 * 2 * K2 * DD, 256), 256>>>(Wl, Wr, Bext);

    cudaEventRecord(evFork, 0);
    cudaStreamWaitEvent(sT, evFork, 0);
    cudaStreamWaitEvent(sM, evFork, 0);

    zero_two<<<2048, 256, 0, sT>>>((float4*)agg_t, aggT4, (float4*)inv_t, NT / 4);
    count_kernel<<<CDIV(NE, 256), 256, 0, sT>>>(e32_mt, (float*)inv_t);
    invert_kernel<<<CDIV(NT, 256), 256, 0, sT>>>((float*)inv_t, NT);

    zero_two<<<2048, 256, 0, sM>>>((float4*)agg_m, aggM4, (float4*)inv_m, NM / 4);
    count_kernel<<<CDIV(NE, 256), 256, 0, sM>>>(e32_tm, (float*)inv_m);
    invert_kernel<<<CDIV(NM, 256), 256, 0, sM>>>((float*)inv_m, NM);

    const float* xm_cur = x_m;
    const float* xt_cur = x_t;
    float* out_m = out;
    float* out_t = out + (size_t)NM * DD;

    for (int layer = 0; layer < 3; layer++) {
        float* xt_next = (layer == 2) ? out_t : ((layer == 0) ? bt0 : bt1);
        float* xm_next = (layer == 2) ? out_m : ((layer == 0) ? bm0 : bm1);
        int relu = (layer < 2) ? 1 : 0;

        // ---- track chain (stream T) ----
        if (layer > 0) {
            zero_kernel<<<2048, 256, 0, sT>>>((float4*)agg_t, aggT4);
            cudaStreamWaitEvent(sT, evGM[layer - 1], 0);
        }
        scatter_bulk<<<scatterBlocks, 256, 0, sT>>>(xm_cur, e32_mt, (float*)inv_t, agg_t);
        gemm_sage_tc<<<CDIV(NT, 128), 256, 0, sT>>>(
            agg_t, xt_cur,
            Bext + (size_t)(layer * 2 + 0) * K2 * DD,
            bl + (size_t)(layer * 2 + 0) * DD,
            xt_next, NT, relu);
        cudaEventRecord(evGT[layer], sT);

        // ---- musician chain (stream M) ----
        if (layer > 0) {
            zero_kernel<<<2048, 256, 0, sM>>>((float4*)agg_m, aggM4);
            cudaStreamWaitEvent(sM, evGT[layer - 1], 0);
        }
        scatter_bulk<<<scatterBlocks, 256, 0, sM>>>(xt_cur, e32_tm, (float*)inv_m, agg_m);
        gemm_sage_tc<<<CDIV(NM, 128), 256, 0, sM>>>(
            agg_m, xm_cur,
            Bext + (size_t)(layer * 2 + 1) * K2 * DD,
            bl + (size_t)(layer * 2 + 1) * DD,
            xm_next, NM, relu);
        cudaEventRecord(evGM[layer], sM);

        xm_cur = xm_next;
        xt_cur = xt_next;
    }

    cudaStreamWaitEvent(0, evGT[2], 0);
    cudaStreamWaitEvent(0, evGM[2], 0);
}

// round 12
// speedup vs baseline: 1.0382x; 1.0382x over previous
#include <cuda_runtime.h>
#include <cstdint>

// Problem constants
#define NM 100000
#define NT 100000
#define NE 400000
#define DD 128
#define K2 256
#define NMAX 100000
#define AGG4 ((size_t)NMAX * DD / 4)   // float4 count per agg buffer

#define CDIV(a,b) (((a)+(b)-1)/(b))

// ---------------- scratch ----------------
__device__ float4 g_agg_t[2 * AGG4];     // double-buffered
__device__ float4 g_agg_m[2 * AGG4];
__device__ float4 g_bm0[AGG4];
__device__ float4 g_bm1[AGG4];
__device__ float4 g_bt0[AGG4];
__device__ float4 g_bt1[AGG4];
__device__ float4 g_inv_t[NT / 4];
__device__ float4 g_inv_m[NM / 4];
__device__ float4 g_Bext[3 * 2 * K2 * DD / 4];   // tf32 bits [lt][k][j]
__device__ int    g_e32_mt[2 * NE];
__device__ int    g_e32_tm[2 * NE];
__device__ int    g_is32;

__device__ __forceinline__ uint32_t f2tf32(float f) {
    uint32_t r;
    asm("cvt.rna.tf32.f32 %0, %1;" : "=r"(r) : "f"(f));
    return r;
}
__device__ __forceinline__ uint32_t smem_u32(const void* p) {
    uint32_t a;
    asm("{ .reg .u64 t; cvta.to.shared.u64 t, %1; cvt.u32.u64 %0, t; }" : "=r"(a) : "l"(p));
    return a;
}

// ---------------- preproc kernels ----------------
__global__ void detect_reset() { g_is32 = 0; }
__global__ void detect_kernel(const unsigned* __restrict__ p) {
    int i = blockIdx.x * blockDim.x + threadIdx.x;
    unsigned v = 0;
    for (int w = i * 2 + 1; w < 2 * NE; w += gridDim.x * blockDim.x * 2) v |= p[w];
    if (__syncthreads_or(v != 0) && threadIdx.x == 0) atomicExch(&g_is32, 1);
}
// convert edges -> int32 AND histogram dst counts (fused)
__global__ void convert_count(const void* __restrict__ e, int* __restrict__ out,
                              float* __restrict__ cnt) {
    int i = blockIdx.x * blockDim.x + threadIdx.x;
    if (i >= 2 * NE) return;
    int v;
    if (g_is32) v = ((const int*)e)[i];
    else        v = (int)((const long long*)e)[i];
    v = min(max(v, 0), NMAX - 1);
    out[i] = v;
    if (i >= NE) atomicAdd(&cnt[v], 1.0f);
}
__global__ void invert_kernel(float* __restrict__ c, int n) {
    int i = blockIdx.x * blockDim.x + threadIdx.x;
    if (i < n) c[i] = 1.0f / fmaxf(c[i], 1.0f);
}
__global__ void zero_two(float4* p0, int n0, float4* p1, int n1) {
    int i = blockIdx.x * blockDim.x + threadIdx.x;
    int stride = gridDim.x * blockDim.x;
    float4 z = make_float4(0.f, 0.f, 0.f, 0.f);
    for (int k = i; k < n0; k += stride) p0[k] = z;
    for (int k = i; k < n1; k += stride) p1[k] = z;
}
__global__ void zero_kernel(float4* p, int n4) {
    int i = blockIdx.x * blockDim.x + threadIdx.x;
    int stride = gridDim.x * blockDim.x;
    float4 z = make_float4(0.f, 0.f, 0.f, 0.f);
    for (; i < n4; i += stride) p[i] = z;
}
// Bext[lt][k][j] = tf32bits( k<128 ? Wl[lt][j][k] : Wr[lt][j][k-128] )
__global__ void prep_weights(const float* __restrict__ Wl,
                             const float* __restrict__ Wr,
                             uint32_t* __restrict__ Bext) {
    int i = blockIdx.x * blockDim.x + threadIdx.x;
    if (i >= 3 * 2 * K2 * DD) return;
    int j  = i % DD;
    int k  = (i / DD) % K2;
    int lt = i / (DD * K2);
    float v = (k < DD) ? Wl[((size_t)lt * DD + j) * DD + k]
                       : Wr[((size_t)lt * DD + j) * DD + (k - DD)];
    Bext[i] = f2tf32(v);
}

// ---------------- scatter via TMA bulk-reduce, inv pre-scaled ----------------
#define EPW 4
__global__ void __launch_bounds__(256)
scatter_bulk(const float* __restrict__ xsrc, const int* __restrict__ edge,
             const float* __restrict__ inv, float* __restrict__ agg) {
    __shared__ __align__(16) float smem[8][EPW][DD];
    const int wInB = threadIdx.x >> 5;
    const int lane = threadIdx.x & 31;
    const int gw = (blockIdx.x * blockDim.x + threadIdx.x) >> 5;
    const int base = gw * EPW;
    if (base >= NE) return;
    const int nE = min(EPW, NE - base);
    const float4* X = (const float4*)xsrc;

#pragma unroll
    for (int j = 0; j < EPW; j++) {
        if (j < nE) {
            int src = edge[base + j];
            float s = inv[edge[NE + base + j]];
            float4 v = X[(size_t)src * (DD / 4) + lane];
            ((float4*)smem[wInB][j])[lane] =
                make_float4(v.x * s, v.y * s, v.z * s, v.w * s);
        }
    }
    __syncwarp();
    if (lane == 0) {
        asm volatile("fence.proxy.async.shared::cta;" ::: "memory");
#pragma unroll
        for (int j = 0; j < EPW; j++) {
            if (j < nE) {
                int dst = edge[NE + base + j];
                float* gp = agg + (size_t)dst * DD;
                uint32_t sa = smem_u32(&smem[wInB][j][0]);
                asm volatile(
                    "cp.reduce.async.bulk.global.shared::cta.bulk_group.add.f32 "
                    "[%0], [%1], %2;" :: "l"(gp), "r"(sa), "r"(DD * 4) : "memory");
            }
        }
        asm volatile("cp.async.bulk.commit_group;" ::: "memory");
        asm volatile("cp.async.bulk.wait_group 0;" ::: "memory");
    }
}

// ---------------- tf32 mma.sync GEMM (R9-proven body; agg prescaled, B tf32) --
__global__ void __launch_bounds__(256)
gemm_sage_tc(const float* __restrict__ Aagg,
             const float* __restrict__ Xdst, const uint32_t* __restrict__ B,
             const float* __restrict__ bias, float* __restrict__ Cout,
             int nRows, int relu) {
    __shared__ uint32_t As[128][36];
    __shared__ uint32_t Bs[32][136];

    const int tid  = threadIdx.x;
    const int wid  = tid >> 5;
    const int lane = tid & 31;
    const int g    = lane >> 2;
    const int t    = lane & 3;
    const int m0   = (wid & 1) * 64;
    const int n0   = (wid >> 1) * 32;
    const int rowBase = blockIdx.x * 128;

    float acc[4][4][4];
#pragma unroll
    for (int im = 0; im < 4; im++)
#pragma unroll
        for (int in = 0; in < 4; in++)
#pragma unroll
            for (int q = 0; q < 4; q++) acc[im][in][q] = 0.f;

    for (int kt = 0; kt < K2; kt += 32) {
#pragma unroll
        for (int p = 0; p < 4; p++) {
            int f = tid + p * 256;
            int r = f >> 3;
            int q = f & 7;
            int gr = rowBase + r;
            if (gr >= nRows) gr = nRows - 1;
            int kg = kt + q * 4;
            const float* src = (kg < DD) ? (Aagg + (size_t)gr * DD + kg)
                                         : (Xdst + (size_t)gr * DD + (kg - DD));
            float4 v = *(const float4*)src;
            As[r][q * 4 + 0] = f2tf32(v.x);
            As[r][q * 4 + 1] = f2tf32(v.y);
            As[r][q * 4 + 2] = f2tf32(v.z);
            As[r][q * 4 + 3] = f2tf32(v.w);
        }
#pragma unroll
        for (int p = 0; p < 4; p++) {
            int f = tid + p * 256;
            int kr = f >> 5;
            int c  = f & 31;
            *(uint4*)&Bs[kr][c * 4] = *(const uint4*)(B + (size_t)(kt + kr) * DD + c * 4);
        }
        __syncthreads();

#pragma unroll
        for (int kk = 0; kk < 32; kk += 8) {
            uint32_t a[4][4], b[4][2];
#pragma unroll
            for (int im = 0; im < 4; im++) {
                int rm = m0 + im * 16 + g;
                a[im][0] = As[rm][kk + t];
                a[im][1] = As[rm + 8][kk + t];
                a[im][2] = As[rm][kk + t + 4];
                a[im][3] = As[rm + 8][kk + t + 4];
            }
#pragma unroll
            for (int in = 0; in < 4; in++) {
                int cn = n0 + in * 8 + g;
                b[in][0] = Bs[kk + t][cn];
                b[in][1] = Bs[kk + t + 4][cn];
            }
#pragma unroll
            for (int im = 0; im < 4; im++)
#pragma unroll
                for (int in = 0; in < 4; in++) {
                    asm volatile(
                        "mma.sync.aligned.m16n8k8.row.col.f32.tf32.tf32.f32 "
                        "{%0,%1,%2,%3}, {%4,%5,%6,%7}, {%8,%9}, {%0,%1,%2,%3};"
                        : "+f"(acc[im][in][0]), "+f"(acc[im][in][1]),
                          "+f"(acc[im][in][2]), "+f"(acc[im][in][3])
                        : "r"(a[im][0]), "r"(a[im][1]), "r"(a[im][2]), "r"(a[im][3]),
                          "r"(b[in][0]), "r"(b[in][1]));
                }
        }
        __syncthreads();
    }

#pragma unroll
    for (int in = 0; in < 4; in++) {
        int col = n0 + in * 8 + 2 * t;
        float b0 = bias[col], b1 = bias[col + 1];
#pragma unroll
        for (int im = 0; im < 4; im++) {
            int r0 = rowBase + m0 + im * 16 + g;
            float v0 = acc[im][in][0] + b0;
            float v1 = acc[im][in][1] + b1;
            float v2 = acc[im][in][2] + b0;
            float v3 = acc[im][in][3] + b1;
            if (relu) {
                v0 = fmaxf(v0, 0.f); v1 = fmaxf(v1, 0.f);
                v2 = fmaxf(v2, 0.f); v3 = fmaxf(v3, 0.f);
            }
            if (r0 < nRows)
                *(float2*)(Cout + (size_t)r0 * DD + col) = make_float2(v0, v1);
            if (r0 + 8 < nRows)
                *(float2*)(Cout + (size_t)(r0 + 8) * DD + col) = make_float2(v2, v3);
        }
    }
}

// ---------------- launch: dependency-minimal two-stream schedule ------------
extern "C" void kernel_launch(void* const* d_in, const int* in_sizes, int n_in,
                              void* d_out, int out_size) {
    static bool s_init = false;
    static cudaStream_t sT, sM;
    static cudaEvent_t evStart, evPre, evGT[3], evGM[3];
    if (!s_init) {
        cudaStreamCreateWithFlags(&sT, cudaStreamNonBlocking);
        cudaStreamCreateWithFlags(&sM, cudaStreamNonBlocking);
        cudaEventCreateWithFlags(&evStart, cudaEventDisableTiming);
        cudaEventCreateWithFlags(&evPre, cudaEventDisableTiming);
        for (int i = 0; i < 3; i++) {
            cudaEventCreateWithFlags(&evGT[i], cudaEventDisableTiming);
            cudaEventCreateWithFlags(&evGM[i], cudaEventDisableTiming);
        }
        s_init = true;
    }

    const float* x_m = (const float*)d_in[0];
    const float* x_t = (const float*)d_in[1];
    const float* Wl  = (const float*)d_in[2];
    const float* bl  = (const float*)d_in[3];
    const float* Wr  = (const float*)d_in[4];
    const void*  e_mt = d_in[5];
    const void*  e_tm = d_in[6];
    float* out = (float*)d_out;

    float *agg_t, *agg_m, *bm0, *bm1, *bt0, *bt1, *inv_t, *inv_m;
    uint32_t* Bext;
    int *e32_mt, *e32_tm;
    cudaGetSymbolAddress((void**)&agg_t, g_agg_t);
    cudaGetSymbolAddress((void**)&agg_m, g_agg_m);
    cudaGetSymbolAddress((void**)&bm0, g_bm0);
    cudaGetSymbolAddress((void**)&bm1, g_bm1);
    cudaGetSymbolAddress((void**)&bt0, g_bt0);
    cudaGetSymbolAddress((void**)&bt1, g_bt1);
    cudaGetSymbolAddress((void**)&inv_t, g_inv_t);
    cudaGetSymbolAddress((void**)&inv_m, g_inv_m);
    cudaGetSymbolAddress((void**)&Bext, g_Bext);
    cudaGetSymbolAddress((void**)&e32_mt, g_e32_mt);
    cudaGetSymbolAddress((void**)&e32_tm, g_e32_tm);

    const int scatterBlocks = CDIV(CDIV(NE, EPW) * 32, 256);
    const int agg4 = (int)AGG4;
    float* aggT[2] = { agg_t, agg_t + AGG4 * 4 };
    float* aggM[2] = { agg_m, agg_m + AGG4 * 4 };

    // ---- fork immediately: side streams zero their agg buffers during preproc
    cudaEventRecord(evStart, 0);
    cudaStreamWaitEvent(sT, evStart, 0);
    cudaStreamWaitEvent(sM, evStart, 0);
    zero_two<<<2048, 256, 0, sT>>>((float4*)aggT[0], agg4, (float4*)aggT[1], agg4);
    zero_two<<<2048, 256, 0, sM>>>((float4*)aggM[0], agg4, (float4*)aggM[1], agg4);

    // ---- preproc on origin stream ----
    detect_reset<<<1, 1>>>();
    zero_two<<<128, 256>>>((float4*)inv_t, NT / 4, (float4*)inv_m, NM / 4);
    detect_kernel<<<256, 256>>>((const unsigned*)e_mt);
    convert_count<<<CDIV(2 * NE, 256), 256>>>(e_mt, e32_mt, (float*)inv_t);
    convert_count<<<CDIV(2 * NE, 256), 256>>>(e_tm, e32_tm, (float*)inv_m);
    invert_kernel<<<CDIV(NT, 256), 256>>>((float*)inv_t, NT);
    invert_kernel<<<CDIV(NM, 256), 256>>>((float*)inv_m, NM);
    prep_weights<<<CDIV(3 * 2 * K2 * DD, 256), 256>>>(Wl, Wr, Bext);
    cudaEventRecord(evPre, 0);
    cudaStreamWaitEvent(sT, evPre, 0);
    cudaStreamWaitEvent(sM, evPre, 0);

    const float* xm_cur = x_m;
    const float* xt_cur = x_t;
    float* out_m = out;
    float* out_t = out + (size_t)NM * DD;

    for (int layer = 0; layer < 3; layer++) {
        const int b = layer & 1;
        float* xt_next = (layer == 2) ? out_t : ((layer == 0) ? bt0 : bt1);
        float* xm_next = (layer == 2) ? out_m : ((layer == 0) ? bm0 : bm1);
        int relu = (layer < 2) ? 1 : 0;

        // ---- track chain (stream T): scatter_T(l) needs gemm_M(l-1) output
        if (layer > 0) cudaStreamWaitEvent(sT, evGM[layer - 1], 0);
        scatter_bulk<<<scatterBlocks, 256, 0, sT>>>(xm_cur, e32_mt, (float*)inv_t, aggT[b]);
        gemm_sage_tc<<<CDIV(NT, 128), 256, 0, sT>>>(
            aggT[b], xt_cur,
            Bext + (size_t)(layer * 2 + 0) * K2 * DD,
            bl + (size_t)(layer * 2 + 0) * DD,
            xt_next, NT, relu);
        cudaEventRecord(evGT[layer], sT);
        if (layer == 0)  // re-zero buffer 0 for layer 2, off critical path
            zero_kernel<<<2048, 256, 0, sT>>>((float4*)aggT[0], agg4);

        // ---- musician chain (stream M): scatter_M(l) needs gemm_T(l-1) output
        if (layer > 0) cudaStreamWaitEvent(sM, evGT[layer - 1], 0);
        scatter_bulk<<<scatterBlocks, 256, 0, sM>>>(xt_cur, e32_tm, (float*)inv_m, aggM[b]);
        gemm_sage_tc<<<CDIV(NM, 128), 256, 0, sM>>>(
            aggM[b], xm_cur,
            Bext + (size_t)(layer * 2 + 1) * K2 * DD,
            bl + (size_t)(layer * 2 + 1) * DD,
            xm_next, NM, relu);
        cudaEventRecord(evGM[layer], sM);
        if (layer == 0)
            zero_kernel<<<2048, 256, 0, sM>>>((float4*)aggM[0], agg4);

        xm_cur = xm_next;
        xt_cur = xt_next;
    }

    cudaStreamWaitEvent(0, evGT[2], 0);
    cudaStreamWaitEvent(0, evGM[2], 0);
}